// round 14
// baseline (speedup 1.0000x reference)
#include <cuda_runtime.h>
#include <math.h>

// Shapes fixed by the dataset: gen_img/target [8,20,1,512,512] f32, gen_D [8,1].
#define NFRAMES   160
#define IMG_H     512
#define IMG_W     512
#define OUT_HW    506            // 512 - 6 (7x7 VALID)
#define NSTRIPS   4              // strips of 127/125 output rows
#define NWARPS    5              // 5 warps x 128 input cols (bases w*100)
#define NTHREADS  (NWARPS * 32)  // 160
#define NBLOCKS   (NSTRIPS * NFRAMES)   // 640

// [0]=sum|d|, [1]=sum d^2, [2]=sum S. Statically zero; the last finishing block
// reads, finalizes, and resets them so every graph replay sees zeros.
__device__ double   g_acc[3] = {0.0, 0.0, 0.0};
__device__ unsigned g_count  = 0;

// ---- packed f32x2 helpers (sm_103a) ----
typedef unsigned long long u64p;

__device__ __forceinline__ u64p pk2(float lo, float hi) {
    u64p r; asm("mov.b64 %0, {%1, %2};" : "=l"(r) : "f"(lo), "f"(hi)); return r;
}
__device__ __forceinline__ void unpk2(u64p v, float& lo, float& hi) {
    asm("mov.b64 {%0, %1}, %2;" : "=f"(lo), "=f"(hi) : "l"(v));
}
__device__ __forceinline__ u64p add2(u64p a, u64p b) {
    u64p r; asm("add.rn.f32x2 %0, %1, %2;" : "=l"(r) : "l"(a), "l"(b)); return r;
}
__device__ __forceinline__ u64p mul2(u64p a, u64p b) {
    u64p r; asm("mul.rn.f32x2 %0, %1, %2;" : "=l"(r) : "l"(a), "l"(b)); return r;
}
__device__ __forceinline__ u64p fma2(u64p a, u64p b, u64p c) {
    u64p r; asm("fma.rn.f32x2 %0, %1, %2, %3;" : "=l"(r) : "l"(a), "l"(b), "l"(c)); return r;
}

__global__ __launch_bounds__(NTHREADS, 5)
void ssim_rec_kernel(const float* __restrict__ X, const float* __restrict__ Y,
                     const float* __restrict__ genD, int nD,
                     float* __restrict__ out) {
    const int strip = blockIdx.x;       // 0..3
    const int frame = blockIdx.y;       // 0..159
    const int lane  = threadIdx.x & 31;
    const int warp  = threadIdx.x >> 5; // 0..4
    const unsigned FULL = 0xffffffffu;

    const int base = warp * 100;                    // float4-aligned
    const int col  = base + 4 * lane;               // first of 4 cols
    const int ccol = min(col, IMG_W - 4);           // clamp (warp 4, lanes 28+)

    // L_rec unique column ownership: warps 0-3 own 100 cols, warp 4 owns 112.
    const bool own = (warp < 4) ? (lane <= 24) : (lane <= 27);
    // SSIM outputs: warps 0-3 own [base, base+100), warp 4 owns [400, 506).
    const bool full4  = (warp < 4) ? (lane <= 24) : (lane <= 25);
    const bool extra2 = (warp == 4) && (lane == 26);   // outputs 504, 505

    // Row strips: 0..2 -> 127 output rows, 3 -> 125. Input rows 133 / 131.
    const int r_start  = strip * 127;
    const int out_rows = (strip == 3) ? 125 : 127;
    const int nrows    = out_rows + 6;
    // rec row ownership (covers all 512 input rows exactly once across strips)
    const int rec_rows = (strip == 3) ? 131 : 127;

    const size_t fbase = (size_t)frame * (IMG_H * IMG_W);
    const float4* xr = (const float4*)(X + fbase + (size_t)r_start * IMG_W) + (ccol >> 2);
    const float4* yr = (const float4*)(Y + fbase + (size_t)r_start * IMG_W) + (ccol >> 2);
    const int rstride = IMG_W / 4;

    const u64p NEG1 = pk2(-1.0f, -1.0f);
    const u64p ZERO = 0ull;
    const u64p ABSM = 0x7fffffff7fffffffull;
    const u64p SGN2 = 0x8000000080000000ull;

    // packed SSIM constants (window-sum space: x49^2 cancels in the ratio)
    const float C1b = 1e-4f * 2401.0f;
    const float C2b = 9e-4f * 2401.0f;
    const float cn  = 49.0f / 48.0f;
    const u64p C1B2 = pk2(C1b, C1b);
    const u64p C2B2 = pk2(C2b, C2b);
    const u64p TWO2 = pk2(2.0f, 2.0f);
    const u64p F492 = pk2(49.0f, 49.0f);
    const u64p CN2P = pk2(2.0f * cn, 2.0f * cn);
    const u64p CNP  = pk2(cn, cn);

    // vertical running window sums (packed by column pairs)
    u64p sxa=ZERO, sxb=ZERO, sya=ZERO, syb=ZERO;
    u64p s2a=ZERO, s2b=ZERO, ska=ZERO, skb=ZERO;

    u64p aab = ZERO, asq = ZERO;      // rec accumulators (packed)
    u64p aSp = ZERO;                  // SSIM accumulator (packed)

// packed 7-window: P0..P3 are per-column moment-PAIR packs for this lane's
// 4 columns; yields W0..W3 (same pairing) for the 4 output columns.
#define HWINP(P0, P1, P2, P3, W0, W1, W2, W3) do {                               \
    u64p s01  = add2(P0, P1);                                                    \
    u64p s012 = add2(s01, P2);                                                   \
    u64p q    = add2(s012, P3);                                                  \
    u64p nq    = __shfl_down_sync(FULL, q,   1);                                 \
    u64p nm3   = __shfl_down_sync(FULL, P3,  1);                                 \
    u64p nnm0  = __shfl_down_sync(FULL, P0,  2);                                 \
    u64p nns01 = __shfl_down_sync(FULL, s01, 2);                                 \
    u64p t = add2(q, nq);                                                        \
    W0 = fma2(nm3,  NEG1, t);                                                    \
    W1 = fma2(P0,   NEG1, t);                                                    \
    W2 = add2(fma2(s01,  NEG1, t), nnm0);                                        \
    W3 = add2(fma2(s012, NEG1, t), nns01);                                       \
} while (0)

// packed SSIM for an output pair; WX,WY,W2m,WK are f32x2 window sums
#define SSIM2(WX, WY, W2m, WK, SLO, SHI) do {                                    \
    u64p t1 = mul2(WX, WY);                                                      \
    u64p A1 = fma2(t1, TWO2, C1B2);                                              \
    u64p qq = fma2(WY, WY, mul2(WX, WX));                                        \
    u64p B1 = add2(qq, C1B2);                                                    \
    u64p t2 = fma2(F492, WK, t1 ^ SGN2);                                         \
    u64p A2 = fma2(CN2P, t2, C2B2);                                              \
    u64p uu = fma2(F492, W2m, qq ^ SGN2);                                        \
    u64p B2 = fma2(CNP, uu, C2B2);                                               \
    u64p num = mul2(A1, A2), den = mul2(B1, B2);                                 \
    float n0,n1,d0,d1; unpk2(num,n0,n1); unpk2(den,d0,d1);                       \
    SLO = __fdividef(n0, d0);  SHI = __fdividef(n1, d1);                         \
} while (0)

#define STEP(P, HAS_OLD, DO_OUT) do {                                            \
    const int _p = (P);                                                          \
    float4 xv = __ldg(xr + (size_t)_p * rstride);                                \
    float4 yv = __ldg(yr + (size_t)_p * rstride);                                \
    float4 xo, yo;                                                               \
    if (HAS_OLD) {                                                               \
        xo = __ldg(xr + (size_t)(_p - 7) * rstride);                             \
        yo = __ldg(yr + (size_t)(_p - 7) * rstride);                             \
    }                                                                            \
    u64p xa = pk2(xv.x, xv.y), xb = pk2(xv.z, xv.w);                             \
    u64p ya = pk2(yv.x, yv.y), yb = pk2(yv.z, yv.w);                             \
    if (own && _p < rec_rows) {   /* L_rec: each pixel exactly once */           \
        u64p da = fma2(ya, NEG1, xa), db = fma2(yb, NEG1, xb);                   \
        aab = add2(aab, da & ABSM);  aab = add2(aab, db & ABSM);                 \
        asq = fma2(da, da, asq);     asq = fma2(db, db, asq);                    \
    }                                                                            \
    /* vertical add of new row */                                                \
    sxa = add2(sxa, xa);  sxb = add2(sxb, xb);                                   \
    sya = add2(sya, ya);  syb = add2(syb, yb);                                   \
    s2a = fma2(ya, ya, fma2(xa, xa, s2a));                                       \
    s2b = fma2(yb, yb, fma2(xb, xb, s2b));                                       \
    ska = fma2(xa, ya, ska);  skb = fma2(xb, yb, skb);                           \
    if (HAS_OLD) {                /* vertical subtract of row p-7 */             \
        u64p oxa = pk2(xo.x, xo.y), oxb = pk2(xo.z, xo.w);                       \
        u64p oya = pk2(yo.x, yo.y), oyb = pk2(yo.z, yo.w);                       \
        u64p nxa = oxa ^ SGN2, nxb = oxb ^ SGN2;                                 \
        u64p nya = oya ^ SGN2, nyb = oyb ^ SGN2;                                 \
        sxa = add2(sxa, nxa);  sxb = add2(sxb, nxb);                             \
        sya = add2(sya, nya);  syb = add2(syb, nyb);                             \
        s2a = fma2(nya, oya, fma2(nxa, oxa, s2a));                               \
        s2b = fma2(nyb, oyb, fma2(nxb, oxb, s2b));                               \
        ska = fma2(nxa, oya, ska);  skb = fma2(nxb, oyb, skb);                   \
    }                                                                            \
    if (DO_OUT) {                                                                \
        /* transpose column-packed vertical sums -> moment-pair packs */         \
        float x0,x1,x2,x3, y0,y1,y2,y3;                                          \
        unpk2(sxa,x0,x1); unpk2(sxb,x2,x3);                                      \
        unpk2(sya,y0,y1); unpk2(syb,y2,y3);                                      \
        u64p PA0=pk2(x0,y0), PA1=pk2(x1,y1), PA2=pk2(x2,y2), PA3=pk2(x3,y3);     \
        float u0,u1,u2,u3, k0,k1,k2,k3;                                          \
        unpk2(s2a,u0,u1); unpk2(s2b,u2,u3);                                      \
        unpk2(ska,k0,k1); unpk2(skb,k2,k3);                                      \
        u64p PB0=pk2(u0,k0), PB1=pk2(u1,k1), PB2=pk2(u2,k2), PB3=pk2(u3,k3);     \
        u64p WA0,WA1,WA2,WA3, WB0,WB1,WB2,WB3;                                   \
        HWINP(PA0,PA1,PA2,PA3, WA0,WA1,WA2,WA3);   /* (WX,WY) per col */         \
        HWINP(PB0,PB1,PB2,PB3, WB0,WB1,WB2,WB3);   /* (W2,WK) per col */         \
        /* transpose back to column-pair packs for SSIM2 */                      \
        float wx0,wy0,wx1,wy1,wx2,wy2,wx3,wy3;                                   \
        unpk2(WA0,wx0,wy0); unpk2(WA1,wx1,wy1);                                  \
        unpk2(WA2,wx2,wy2); unpk2(WA3,wx3,wy3);                                  \
        float w20,wk0,w21,wk1,w22,wk2,w23,wk3;                                   \
        unpk2(WB0,w20,wk0); unpk2(WB1,w21,wk1);                                  \
        unpk2(WB2,w22,wk2); unpk2(WB3,w23,wk3);                                  \
        float S0, S1, S2, S3;                                                    \
        {   u64p pWX = pk2(wx0,wx1), pWY = pk2(wy0,wy1);                         \
            u64p pW2 = pk2(w20,w21), pWK = pk2(wk0,wk1);                         \
            SSIM2(pWX, pWY, pW2, pWK, S0, S1); }                                 \
        {   u64p pWX = pk2(wx2,wx3), pWY = pk2(wy2,wy3);                         \
            u64p pW2 = pk2(w22,w23), pWK = pk2(wk2,wk3);                         \
            SSIM2(pWX, pWY, pW2, pWK, S2, S3); }                                 \
        if (full4) {                                                             \
            aSp = add2(aSp, pk2(S0, S1));                                        \
            aSp = add2(aSp, pk2(S2, S3));                                        \
        } else if (extra2) {                                                     \
            aSp = add2(aSp, pk2(S0, S1));                                        \
        }                                                                        \
    }                                                                            \
} while (0)

    // prologue: rows 0..5 fill the vertical window (rec active; rec_rows > 5)
    STEP(0, false, false); STEP(1, false, false); STEP(2, false, false);
    STEP(3, false, false); STEP(4, false, false); STEP(5, false, false);
    // first output row: window rows 0..6, nothing to subtract yet
    STEP(6, false, true);
    // steady state: (nrows - 7) is even for both strip kinds (126 / 124)
    for (int p = 7; p < nrows; p += 2) {
        STEP(p,     true, true);
        STEP(p + 1, true, true);
    }
#undef STEP
#undef HWINP
#undef SSIM2

    // ---- block reduction ----
    float ab0, ab1, sq0, sq1, sS0, sS1;
    unpk2(aab, ab0, ab1);  unpk2(asq, sq0, sq1);  unpk2(aSp, sS0, sS1);
    float a_abs = ab0 + ab1, a_sq = sq0 + sq1, a_S = sS0 + sS1;

#pragma unroll
    for (int off = 16; off > 0; off >>= 1) {
        a_abs += __shfl_down_sync(FULL, a_abs, off);
        a_sq  += __shfl_down_sync(FULL, a_sq,  off);
        a_S   += __shfl_down_sync(FULL, a_S,   off);
    }
    __shared__ float s_abs[NWARPS], s_sq[NWARPS], s_S[NWARPS];
    if (lane == 0) { s_abs[warp] = a_abs; s_sq[warp] = a_sq; s_S[warp] = a_S; }
    __syncthreads();
    if (threadIdx.x == 0) {
        float t_abs = 0.f, t_sq = 0.f, t_S = 0.f;
#pragma unroll
        for (int i = 0; i < NWARPS; ++i) {
            t_abs += s_abs[i]; t_sq += s_sq[i]; t_S += s_S[i];
        }
        atomicAdd(&g_acc[0], (double)t_abs);
        atomicAdd(&g_acc[1], (double)t_sq);
        atomicAdd(&g_acc[2], (double)t_S);

        // ---- fused finalize: last block to finish computes the outputs ----
        __threadfence();
        unsigned ticket = atomicAdd(&g_count, 1u);
        if (ticket == NBLOCKS - 1) {
            __threadfence();
            double a0 = *(volatile double*)&g_acc[0];
            double a1 = *(volatile double*)&g_acc[1];
            double a2 = *(volatile double*)&g_acc[2];

            const double Ntot  = (double)NFRAMES * IMG_H * IMG_W;
            const double Nssim = (double)NFRAMES * OUT_HW * OUT_HW;

            double L_rec  = a0 / Ntot + a1 / Ntot;
            double L_ssim = a2 / Nssim;

            double s = 0.0;
            for (int i = 0; i < nD; ++i) s += (double)genD[i];
            double L_adv = -s / (double)nD;

            double L_total = L_rec + 0.01 * (1.0 - L_ssim) + 1e-4 * L_adv;

            out[0] = (float)L_total;
            out[1] = (float)L_rec;
            out[2] = (float)L_ssim;
            out[3] = (float)L_adv;

            // reset for the next graph replay
            *(volatile double*)&g_acc[0] = 0.0;
            *(volatile double*)&g_acc[1] = 0.0;
            *(volatile double*)&g_acc[2] = 0.0;
            __threadfence();
            *(volatile unsigned*)&g_count = 0u;
        }
    }
}

extern "C" void kernel_launch(void* const* d_in, const int* in_sizes, int n_in,
                              void* d_out, int out_size) {
    const float* gen_img = (const float*)d_in[0];
    const float* target  = (const float*)d_in[1];
    const float* gen_D   = (const float*)d_in[2];
    float* out = (float*)d_out;
    const int nD = in_sizes[2];

    dim3 grid(NSTRIPS, NFRAMES);
    ssim_rec_kernel<<<grid, NTHREADS>>>(gen_img, target, gen_D, nD, out);
}

// round 15
// speedup vs baseline: 1.1265x; 1.1265x over previous
#include <cuda_runtime.h>
#include <math.h>

// Shapes fixed by the dataset: gen_img/target [8,20,1,512,512] f32, gen_D [8,1].
#define NFRAMES   160
#define IMG_H     512
#define IMG_W     512
#define OUT_HW    506            // 512 - 6 (7x7 VALID)
#define NSTRIPS   4              // strips of 127/125 output rows
#define NWARPS    5              // 5 warps x 128 input cols (bases w*100)
#define NTHREADS  (NWARPS * 32)  // 160
#define NBLOCKS   (NSTRIPS * NFRAMES)   // 640

// [0]=sum|d|, [1]=sum d^2, [2]=sum S. Statically zero; the last finishing block
// reads, finalizes, and resets them so every graph replay sees zeros.
__device__ double   g_acc[3] = {0.0, 0.0, 0.0};
__device__ unsigned g_count  = 0;

// ---- packed f32x2 helpers (sm_103a) ----
typedef unsigned long long u64p;

__device__ __forceinline__ u64p pk2(float lo, float hi) {
    u64p r; asm("mov.b64 %0, {%1, %2};" : "=l"(r) : "f"(lo), "f"(hi)); return r;
}
__device__ __forceinline__ void unpk2(u64p v, float& lo, float& hi) {
    asm("mov.b64 {%0, %1}, %2;" : "=f"(lo), "=f"(hi) : "l"(v));
}
__device__ __forceinline__ u64p add2(u64p a, u64p b) {
    u64p r; asm("add.rn.f32x2 %0, %1, %2;" : "=l"(r) : "l"(a), "l"(b)); return r;
}
__device__ __forceinline__ u64p mul2(u64p a, u64p b) {
    u64p r; asm("mul.rn.f32x2 %0, %1, %2;" : "=l"(r) : "l"(a), "l"(b)); return r;
}
__device__ __forceinline__ u64p fma2(u64p a, u64p b, u64p c) {
    u64p r; asm("fma.rn.f32x2 %0, %1, %2, %3;" : "=l"(r) : "l"(a), "l"(b), "l"(c)); return r;
}

__global__ __launch_bounds__(NTHREADS, 5)
void ssim_rec_kernel(const float* __restrict__ X, const float* __restrict__ Y,
                     const float* __restrict__ genD, int nD,
                     float* __restrict__ out) {
    const int strip = blockIdx.x;       // 0..3
    const int frame = blockIdx.y;       // 0..159
    const int lane  = threadIdx.x & 31;
    const int warp  = threadIdx.x >> 5; // 0..4
    const unsigned FULL = 0xffffffffu;

    const int base = warp * 100;                    // float4-aligned
    const int col  = base + 4 * lane;               // first of 4 cols
    const int ccol = min(col, IMG_W - 4);           // clamp (warp 4, lanes 28+)

    // L_rec unique column ownership: warps 0-3 own 100 cols, warp 4 owns 112.
    const bool own = (warp < 4) ? (lane <= 24) : (lane <= 27);
    // SSIM outputs: warps 0-3 own [base, base+100), warp 4 owns [400, 506).
    const bool full4  = (warp < 4) ? (lane <= 24) : (lane <= 25);
    const bool extra2 = (warp == 4) && (lane == 26);   // outputs 504, 505

    // Row strips: 0..2 -> 127 output rows, 3 -> 125. Input rows 133 / 131.
    const int r_start  = strip * 127;
    const int out_rows = (strip == 3) ? 125 : 127;
    const int nrows    = out_rows + 6;
    // rec row ownership (covers all 512 input rows exactly once across strips)
    const int rec_rows = (strip == 3) ? 131 : 127;

    const size_t fbase = (size_t)frame * (IMG_H * IMG_W);
    const float4* xr = (const float4*)(X + fbase + (size_t)r_start * IMG_W) + (ccol >> 2);
    const float4* yr = (const float4*)(Y + fbase + (size_t)r_start * IMG_W) + (ccol >> 2);
    const int rstride = IMG_W / 4;

    const u64p NEG1 = pk2(-1.0f, -1.0f);
    const u64p ZERO = 0ull;
    const u64p ABSM = 0x7fffffff7fffffffull;
    const u64p SGN2 = 0x8000000080000000ull;

    // packed SSIM constants (window-sum space: x49^2 cancels in the ratio)
    const float C1b = 1e-4f * 2401.0f;
    const float C2b = 9e-4f * 2401.0f;
    const float cn  = 49.0f / 48.0f;
    const u64p C1B2 = pk2(C1b, C1b);
    const u64p C2B2 = pk2(C2b, C2b);
    const u64p TWO2 = pk2(2.0f, 2.0f);
    const u64p F492 = pk2(49.0f, 49.0f);
    const u64p CN2P = pk2(2.0f * cn, 2.0f * cn);
    const u64p CNP  = pk2(cn, cn);

    // vertical running window sums (packed by column pairs)
    u64p sxa=ZERO, sxb=ZERO, sya=ZERO, syb=ZERO;
    u64p s2a=ZERO, s2b=ZERO, ska=ZERO, skb=ZERO;

    u64p aab = ZERO, asq = ZERO;      // rec accumulators (packed)
    float a_S = 0.f;

// horizontal 7-window for 4 outputs from packed moments A=(m0,m1), B=(m2,m3)
#define HWIN(A, B, W0, W1, W2, W3) do {                                          \
    float m0,m1,m2,m3; unpk2(A,m0,m1); unpk2(B,m2,m3);                           \
    float s01 = m0 + m1, s012 = s01 + m2, q = s012 + m3;                         \
    float nq    = __shfl_down_sync(FULL, q,   1);                                \
    float nm3   = __shfl_down_sync(FULL, m3,  1);                                \
    float nnm0  = __shfl_down_sync(FULL, m0,  2);                                \
    float nns01 = __shfl_down_sync(FULL, s01, 2);                                \
    float t = q + nq;                                                            \
    W0 = t - nm3;                                                                \
    W1 = t - m0;                                                                 \
    W2 = (t - s01)  + nnm0;                                                      \
    W3 = (t - s012) + nns01;                                                     \
} while (0)

// packed SSIM for an output pair; WX,WY,W2m,WK are f32x2 window sums
#define SSIM2(WX, WY, W2m, WK, SLO, SHI) do {                                    \
    u64p t1 = mul2(WX, WY);                                                      \
    u64p A1 = fma2(t1, TWO2, C1B2);                                              \
    u64p qq = fma2(WY, WY, mul2(WX, WX));                                        \
    u64p B1 = add2(qq, C1B2);                                                    \
    u64p t2 = fma2(F492, WK, t1 ^ SGN2);                                         \
    u64p A2 = fma2(CN2P, t2, C2B2);                                              \
    u64p uu = fma2(F492, W2m, qq ^ SGN2);                                        \
    u64p B2 = fma2(CNP, uu, C2B2);                                               \
    u64p num = mul2(A1, A2), den = mul2(B1, B2);                                 \
    float n0,n1,d0,d1; unpk2(num,n0,n1); unpk2(den,d0,d1);                       \
    SLO = __fdividef(n0, d0);  SHI = __fdividef(n1, d1);                         \
} while (0)

#define STEP(P, HAS_OLD, DO_OUT) do {                                            \
    const int _p = (P);                                                          \
    float4 xv = __ldg(xr + (size_t)_p * rstride);                                \
    float4 yv = __ldg(yr + (size_t)_p * rstride);                                \
    float4 xo, yo;                                                               \
    if (HAS_OLD) {                                                               \
        xo = __ldg(xr + (size_t)(_p - 7) * rstride);                             \
        yo = __ldg(yr + (size_t)(_p - 7) * rstride);                             \
    }                                                                            \
    u64p xa = pk2(xv.x, xv.y), xb = pk2(xv.z, xv.w);                             \
    u64p ya = pk2(yv.x, yv.y), yb = pk2(yv.z, yv.w);                             \
    if (own && _p < rec_rows) {   /* L_rec: each pixel exactly once */           \
        u64p da = fma2(ya, NEG1, xa), db = fma2(yb, NEG1, xb);                   \
        aab = add2(aab, da & ABSM);  aab = add2(aab, db & ABSM);                 \
        asq = fma2(da, da, asq);     asq = fma2(db, db, asq);                    \
    }                                                                            \
    /* vertical add of new row */                                                \
    sxa = add2(sxa, xa);  sxb = add2(sxb, xb);                                   \
    sya = add2(sya, ya);  syb = add2(syb, yb);                                   \
    s2a = add2(s2a, fma2(ya, ya, mul2(xa, xa)));                                 \
    s2b = add2(s2b, fma2(yb, yb, mul2(xb, xb)));                                 \
    ska = fma2(xa, ya, ska);  skb = fma2(xb, yb, skb);                           \
    if (HAS_OLD) {                /* vertical subtract of row p-7 */             \
        u64p oxa = pk2(xo.x, xo.y), oxb = pk2(xo.z, xo.w);                       \
        u64p oya = pk2(yo.x, yo.y), oyb = pk2(yo.z, yo.w);                       \
        sxa = fma2(oxa, NEG1, sxa);  sxb = fma2(oxb, NEG1, sxb);                 \
        sya = fma2(oya, NEG1, sya);  syb = fma2(oyb, NEG1, syb);                 \
        s2a = fma2(fma2(oya, oya, mul2(oxa, oxa)), NEG1, s2a);                   \
        s2b = fma2(fma2(oyb, oyb, mul2(oxb, oxb)), NEG1, s2b);                   \
        ska = fma2(mul2(oxa, oya), NEG1, ska);                                   \
        skb = fma2(mul2(oxb, oyb), NEG1, skb);                                   \
    }                                                                            \
    if (DO_OUT) {                                                                \
        float WX0,WX1,WX2,WX3, WY0,WY1,WY2,WY3;                                  \
        float W20,W21,W22,W23, WK0,WK1,WK2,WK3;                                  \
        HWIN(sxa, sxb, WX0, WX1, WX2, WX3);                                      \
        HWIN(sya, syb, WY0, WY1, WY2, WY3);                                      \
        HWIN(s2a, s2b, W20, W21, W22, W23);                                      \
        HWIN(ska, skb, WK0, WK1, WK2, WK3);                                      \
        float S0, S1, S2, S3;                                                    \
        {   u64p pWX = pk2(WX0, WX1), pWY = pk2(WY0, WY1);                       \
            u64p pW2 = pk2(W20, W21), pWK = pk2(WK0, WK1);                       \
            SSIM2(pWX, pWY, pW2, pWK, S0, S1); }                                 \
        {   u64p pWX = pk2(WX2, WX3), pWY = pk2(WY2, WY3);                       \
            u64p pW2 = pk2(W22, W23), pWK = pk2(WK2, WK3);                       \
            SSIM2(pWX, pWY, pW2, pWK, S2, S3); }                                 \
        if (full4)       a_S += (S0 + S1) + (S2 + S3);                           \
        else if (extra2) a_S += S0 + S1;                                         \
    }                                                                            \
} while (0)

    // prologue: rows 0..5 fill the vertical window (rec active; rec_rows > 5)
    STEP(0, false, false); STEP(1, false, false); STEP(2, false, false);
    STEP(3, false, false); STEP(4, false, false); STEP(5, false, false);
    // first output row: window rows 0..6, nothing to subtract yet
    STEP(6, false, true);
    // steady state: (nrows - 7) is even for both strip kinds (126 / 124)
    for (int p = 7; p < nrows; p += 2) {
        STEP(p,     true, true);
        STEP(p + 1, true, true);
    }
#undef STEP
#undef HWIN
#undef SSIM2

    // ---- block reduction ----
    float ab0, ab1, sq0, sq1;
    unpk2(aab, ab0, ab1);  unpk2(asq, sq0, sq1);
    float a_abs = ab0 + ab1, a_sq = sq0 + sq1;

#pragma unroll
    for (int off = 16; off > 0; off >>= 1) {
        a_abs += __shfl_down_sync(FULL, a_abs, off);
        a_sq  += __shfl_down_sync(FULL, a_sq,  off);
        a_S   += __shfl_down_sync(FULL, a_S,   off);
    }
    __shared__ float s_abs[NWARPS], s_sq[NWARPS], s_S[NWARPS];
    if (lane == 0) { s_abs[warp] = a_abs; s_sq[warp] = a_sq; s_S[warp] = a_S; }
    __syncthreads();
    if (threadIdx.x == 0) {
        float t_abs = 0.f, t_sq = 0.f, t_S = 0.f;
#pragma unroll
        for (int i = 0; i < NWARPS; ++i) {
            t_abs += s_abs[i]; t_sq += s_sq[i]; t_S += s_S[i];
        }
        atomicAdd(&g_acc[0], (double)t_abs);
        atomicAdd(&g_acc[1], (double)t_sq);
        atomicAdd(&g_acc[2], (double)t_S);

        // ---- fused finalize: last block to finish computes the outputs ----
        __threadfence();
        unsigned ticket = atomicAdd(&g_count, 1u);
        if (ticket == NBLOCKS - 1) {
            __threadfence();
            double a0 = *(volatile double*)&g_acc[0];
            double a1 = *(volatile double*)&g_acc[1];
            double a2 = *(volatile double*)&g_acc[2];

            const double Ntot  = (double)NFRAMES * IMG_H * IMG_W;
            const double Nssim = (double)NFRAMES * OUT_HW * OUT_HW;

            double L_rec  = a0 / Ntot + a1 / Ntot;
            double L_ssim = a2 / Nssim;

            double s = 0.0;
            for (int i = 0; i < nD; ++i) s += (double)genD[i];
            double L_adv = -s / (double)nD;

            double L_total = L_rec + 0.01 * (1.0 - L_ssim) + 1e-4 * L_adv;

            out[0] = (float)L_total;
            out[1] = (float)L_rec;
            out[2] = (float)L_ssim;
            out[3] = (float)L_adv;

            // reset for the next graph replay
            *(volatile double*)&g_acc[0] = 0.0;
            *(volatile double*)&g_acc[1] = 0.0;
            *(volatile double*)&g_acc[2] = 0.0;
            __threadfence();
            *(volatile unsigned*)&g_count = 0u;
        }
    }
}

extern "C" void kernel_launch(void* const* d_in, const int* in_sizes, int n_in,
                              void* d_out, int out_size) {
    const float* gen_img = (const float*)d_in[0];
    const float* target  = (const float*)d_in[1];
    const float* gen_D   = (const float*)d_in[2];
    float* out = (float*)d_out;
    const int nD = in_sizes[2];

    dim3 grid(NSTRIPS, NFRAMES);
    ssim_rec_kernel<<<grid, NTHREADS>>>(gen_img, target, gen_D, nD, out);
}

// round 16
// speedup vs baseline: 1.1638x; 1.0332x over previous
#include <cuda_runtime.h>
#include <math.h>

// Shapes fixed by the dataset: gen_img/target [8,20,1,512,512] f32, gen_D [8,1].
#define NFRAMES   160
#define IMG_H     512
#define IMG_W     512
#define OUT_HW    506            // 512 - 6 (7x7 VALID)
#define NSTRIPS   8              // strips of 64/58 output rows
#define NWARPS    5              // 5 warps x 128 input cols (bases w*100)
#define NTHREADS  (NWARPS * 32)  // 160
#define NBLOCKS   (NSTRIPS * NFRAMES)   // 1280

// [0]=sum|d|, [1]=sum d^2, [2]=sum S. Statically zero; the last finishing block
// reads, finalizes, and resets them so every graph replay sees zeros.
__device__ double   g_acc[3] = {0.0, 0.0, 0.0};
__device__ unsigned g_count  = 0;

// ---- packed f32x2 helpers (sm_103a) ----
typedef unsigned long long u64p;

__device__ __forceinline__ u64p pk2(float lo, float hi) {
    u64p r; asm("mov.b64 %0, {%1, %2};" : "=l"(r) : "f"(lo), "f"(hi)); return r;
}
__device__ __forceinline__ void unpk2(u64p v, float& lo, float& hi) {
    asm("mov.b64 {%0, %1}, %2;" : "=f"(lo), "=f"(hi) : "l"(v));
}
__device__ __forceinline__ u64p add2(u64p a, u64p b) {
    u64p r; asm("add.rn.f32x2 %0, %1, %2;" : "=l"(r) : "l"(a), "l"(b)); return r;
}
__device__ __forceinline__ u64p mul2(u64p a, u64p b) {
    u64p r; asm("mul.rn.f32x2 %0, %1, %2;" : "=l"(r) : "l"(a), "l"(b)); return r;
}
__device__ __forceinline__ u64p fma2(u64p a, u64p b, u64p c) {
    u64p r; asm("fma.rn.f32x2 %0, %1, %2, %3;" : "=l"(r) : "l"(a), "l"(b), "l"(c)); return r;
}

__global__ __launch_bounds__(NTHREADS, 6)
void ssim_rec_kernel(const float* __restrict__ X, const float* __restrict__ Y,
                     const float* __restrict__ genD, int nD,
                     float* __restrict__ out) {
    const int strip = blockIdx.x;       // 0..7
    const int frame = blockIdx.y;       // 0..159
    const int lane  = threadIdx.x & 31;
    const int warp  = threadIdx.x >> 5; // 0..4
    const unsigned FULL = 0xffffffffu;

    const int base = warp * 100;                    // float4-aligned
    const int col  = base + 4 * lane;               // first of 4 cols
    const int ccol = min(col, IMG_W - 4);           // clamp (warp 4, lanes 28+)

    // L_rec unique column ownership: warps 0-3 own 100 cols, warp 4 owns 112.
    const bool own = (warp < 4) ? (lane <= 24) : (lane <= 27);
    // SSIM outputs: warps 0-3 own [base, base+100), warp 4 owns [400, 506).
    const bool full4  = (warp < 4) ? (lane <= 24) : (lane <= 25);
    const bool extra2 = (warp == 4) && (lane == 26);   // outputs 504, 505

    // Row strips: 0..6 -> 64 output rows, 7 -> 58. Input rows 70 / 64.
    const int r_start  = strip * 64;
    const int out_rows = (strip == 7) ? 58 : 64;
    const int nrows    = out_rows + 6;
    // rec row ownership: every strip owns exactly its 64 input rows
    const int rec_rows = 64;

    const size_t fbase = (size_t)frame * (IMG_H * IMG_W);
    const float4* xr = (const float4*)(X + fbase + (size_t)r_start * IMG_W) + (ccol >> 2);
    const float4* yr = (const float4*)(Y + fbase + (size_t)r_start * IMG_W) + (ccol >> 2);
    const int rstride = IMG_W / 4;

    const u64p NEG1 = pk2(-1.0f, -1.0f);
    const u64p ZERO = 0ull;
    const u64p ABSM = 0x7fffffff7fffffffull;
    const u64p SGN2 = 0x8000000080000000ull;

    // packed SSIM constants (window-sum space: x49^2 cancels in the ratio)
    const float C1b = 1e-4f * 2401.0f;
    const float C2b = 9e-4f * 2401.0f;
    const float cn  = 49.0f / 48.0f;
    const u64p C1B2 = pk2(C1b, C1b);
    const u64p C2B2 = pk2(C2b, C2b);
    const u64p TWO2 = pk2(2.0f, 2.0f);
    const u64p F492 = pk2(49.0f, 49.0f);
    const u64p CN2P = pk2(2.0f * cn, 2.0f * cn);
    const u64p CNP  = pk2(cn, cn);

    // vertical running window sums (packed by column pairs)
    u64p sxa=ZERO, sxb=ZERO, sya=ZERO, syb=ZERO;
    u64p s2a=ZERO, s2b=ZERO, ska=ZERO, skb=ZERO;

    u64p aab = ZERO, asq = ZERO;      // rec accumulators (packed)
    float a_S = 0.f;

// horizontal 7-window for 4 outputs from packed moments A=(m0,m1), B=(m2,m3)
#define HWIN(A, B, W0, W1, W2, W3) do {                                          \
    float m0,m1,m2,m3; unpk2(A,m0,m1); unpk2(B,m2,m3);                           \
    float s01 = m0 + m1, s012 = s01 + m2, q = s012 + m3;                         \
    float nq    = __shfl_down_sync(FULL, q,   1);                                \
    float nm3   = __shfl_down_sync(FULL, m3,  1);                                \
    float nnm0  = __shfl_down_sync(FULL, m0,  2);                                \
    float nns01 = __shfl_down_sync(FULL, s01, 2);                                \
    float t = q + nq;                                                            \
    W0 = t - nm3;                                                                \
    W1 = t - m0;                                                                 \
    W2 = (t - s01)  + nnm0;                                                      \
    W3 = (t - s012) + nns01;                                                     \
} while (0)

// packed SSIM for an output pair; WX,WY,W2m,WK are f32x2 window sums
#define SSIM2(WX, WY, W2m, WK, SLO, SHI) do {                                    \
    u64p t1 = mul2(WX, WY);                                                      \
    u64p A1 = fma2(t1, TWO2, C1B2);                                              \
    u64p qq = fma2(WY, WY, mul2(WX, WX));                                        \
    u64p B1 = add2(qq, C1B2);                                                    \
    u64p t2 = fma2(F492, WK, t1 ^ SGN2);                                         \
    u64p A2 = fma2(CN2P, t2, C2B2);                                              \
    u64p uu = fma2(F492, W2m, qq ^ SGN2);                                        \
    u64p B2 = fma2(CNP, uu, C2B2);                                               \
    u64p num = mul2(A1, A2), den = mul2(B1, B2);                                 \
    float n0,n1,d0,d1; unpk2(num,n0,n1); unpk2(den,d0,d1);                       \
    SLO = __fdividef(n0, d0);  SHI = __fdividef(n1, d1);                         \
} while (0)

#define STEP(P, HAS_OLD, DO_OUT) do {                                            \
    const int _p = (P);                                                          \
    float4 xv = __ldg(xr + (size_t)_p * rstride);                                \
    float4 yv = __ldg(yr + (size_t)_p * rstride);                                \
    float4 xo, yo;                                                               \
    if (HAS_OLD) {                                                               \
        xo = __ldg(xr + (size_t)(_p - 7) * rstride);                             \
        yo = __ldg(yr + (size_t)(_p - 7) * rstride);                             \
    }                                                                            \
    u64p xa = pk2(xv.x, xv.y), xb = pk2(xv.z, xv.w);                             \
    u64p ya = pk2(yv.x, yv.y), yb = pk2(yv.z, yv.w);                             \
    if (own && _p < rec_rows) {   /* L_rec: each pixel exactly once */           \
        u64p da = fma2(ya, NEG1, xa), db = fma2(yb, NEG1, xb);                   \
        aab = add2(aab, da & ABSM);  aab = add2(aab, db & ABSM);                 \
        asq = fma2(da, da, asq);     asq = fma2(db, db, asq);                    \
    }                                                                            \
    /* vertical add of new row */                                                \
    sxa = add2(sxa, xa);  sxb = add2(sxb, xb);                                   \
    sya = add2(sya, ya);  syb = add2(syb, yb);                                   \
    s2a = add2(s2a, fma2(ya, ya, mul2(xa, xa)));                                 \
    s2b = add2(s2b, fma2(yb, yb, mul2(xb, xb)));                                 \
    ska = fma2(xa, ya, ska);  skb = fma2(xb, yb, skb);                           \
    if (HAS_OLD) {                /* vertical subtract of row p-7 */             \
        u64p oxa = pk2(xo.x, xo.y), oxb = pk2(xo.z, xo.w);                       \
        u64p oya = pk2(yo.x, yo.y), oyb = pk2(yo.z, yo.w);                       \
        sxa = fma2(oxa, NEG1, sxa);  sxb = fma2(oxb, NEG1, sxb);                 \
        sya = fma2(oya, NEG1, sya);  syb = fma2(oyb, NEG1, syb);                 \
        s2a = fma2(fma2(oya, oya, mul2(oxa, oxa)), NEG1, s2a);                   \
        s2b = fma2(fma2(oyb, oyb, mul2(oxb, oxb)), NEG1, s2b);                   \
        ska = fma2(mul2(oxa, oya), NEG1, ska);                                   \
        skb = fma2(mul2(oxb, oyb), NEG1, skb);                                   \
    }                                                                            \
    if (DO_OUT) {                                                                \
        float WX0,WX1,WX2,WX3, WY0,WY1,WY2,WY3;                                  \
        float W20,W21,W22,W23, WK0,WK1,WK2,WK3;                                  \
        HWIN(sxa, sxb, WX0, WX1, WX2, WX3);                                      \
        HWIN(sya, syb, WY0, WY1, WY2, WY3);                                      \
        HWIN(s2a, s2b, W20, W21, W22, W23);                                      \
        HWIN(ska, skb, WK0, WK1, WK2, WK3);                                      \
        float S0, S1, S2, S3;                                                    \
        {   u64p pWX = pk2(WX0, WX1), pWY = pk2(WY0, WY1);                       \
            u64p pW2 = pk2(W20, W21), pWK = pk2(WK0, WK1);                       \
            SSIM2(pWX, pWY, pW2, pWK, S0, S1); }                                 \
        {   u64p pWX = pk2(WX2, WX3), pWY = pk2(WY2, WY3);                       \
            u64p pW2 = pk2(W22, W23), pWK = pk2(WK2, WK3);                       \
            SSIM2(pWX, pWY, pW2, pWK, S2, S3); }                                 \
        if (full4)       a_S += (S0 + S1) + (S2 + S3);                           \
        else if (extra2) a_S += S0 + S1;                                         \
    }                                                                            \
} while (0)

    // prologue: rows 0..5 fill the vertical window (rec active)
    STEP(0, false, false); STEP(1, false, false); STEP(2, false, false);
    STEP(3, false, false); STEP(4, false, false); STEP(5, false, false);
    // first output row: window rows 0..6, nothing to subtract yet
    STEP(6, false, true);
    // steady state (nrows-7 is odd: 63 or 57): pairs then one trailing step
    int p = 7;
    for (; p + 1 < nrows; p += 2) {
        STEP(p,     true, true);
        STEP(p + 1, true, true);
    }
    if (p < nrows) STEP(p, true, true);
#undef STEP
#undef HWIN
#undef SSIM2

    // ---- block reduction ----
    float ab0, ab1, sq0, sq1;
    unpk2(aab, ab0, ab1);  unpk2(asq, sq0, sq1);
    float a_abs = ab0 + ab1, a_sq = sq0 + sq1;

#pragma unroll
    for (int off = 16; off > 0; off >>= 1) {
        a_abs += __shfl_down_sync(FULL, a_abs, off);
        a_sq  += __shfl_down_sync(FULL, a_sq,  off);
        a_S   += __shfl_down_sync(FULL, a_S,   off);
    }
    __shared__ float s_abs[NWARPS], s_sq[NWARPS], s_S[NWARPS];
    if (lane == 0) { s_abs[warp] = a_abs; s_sq[warp] = a_sq; s_S[warp] = a_S; }
    __syncthreads();
    if (threadIdx.x == 0) {
        float t_abs = 0.f, t_sq = 0.f, t_S = 0.f;
#pragma unroll
        for (int i = 0; i < NWARPS; ++i) {
            t_abs += s_abs[i]; t_sq += s_sq[i]; t_S += s_S[i];
        }
        atomicAdd(&g_acc[0], (double)t_abs);
        atomicAdd(&g_acc[1], (double)t_sq);
        atomicAdd(&g_acc[2], (double)t_S);

        // ---- fused finalize: last block to finish computes the outputs ----
        __threadfence();
        unsigned ticket = atomicAdd(&g_count, 1u);
        if (ticket == NBLOCKS - 1) {
            __threadfence();
            double a0 = *(volatile double*)&g_acc[0];
            double a1 = *(volatile double*)&g_acc[1];
            double a2 = *(volatile double*)&g_acc[2];

            const double Ntot  = (double)NFRAMES * IMG_H * IMG_W;
            const double Nssim = (double)NFRAMES * OUT_HW * OUT_HW;

            double L_rec  = a0 / Ntot + a1 / Ntot;
            double L_ssim = a2 / Nssim;

            double s = 0.0;
            for (int i = 0; i < nD; ++i) s += (double)genD[i];
            double L_adv = -s / (double)nD;

            double L_total = L_rec + 0.01 * (1.0 - L_ssim) + 1e-4 * L_adv;

            out[0] = (float)L_total;
            out[1] = (float)L_rec;
            out[2] = (float)L_ssim;
            out[3] = (float)L_adv;

            // reset for the next graph replay
            *(volatile double*)&g_acc[0] = 0.0;
            *(volatile double*)&g_acc[1] = 0.0;
            *(volatile double*)&g_acc[2] = 0.0;
            __threadfence();
            *(volatile unsigned*)&g_count = 0u;
        }
    }
}

extern "C" void kernel_launch(void* const* d_in, const int* in_sizes, int n_in,
                              void* d_out, int out_size) {
    const float* gen_img = (const float*)d_in[0];
    const float* target  = (const float*)d_in[1];
    const float* gen_D   = (const float*)d_in[2];
    float* out = (float*)d_out;
    const int nD = in_sizes[2];

    dim3 grid(NSTRIPS, NFRAMES);
    ssim_rec_kernel<<<grid, NTHREADS>>>(gen_img, target, gen_D, nD, out);
}